// round 10
// baseline (speedup 1.0000x reference)
#include <cuda_runtime.h>

#define Bc      128
#define Sc      37
#define Tc      2048
#define Dc      256
#define STc     8
#define Cc      2
#define Fc      (2 * Sc)        // 74
#define MERGEDc (Dc + STc)      // 264
#define SPLIT   4
#define CHUNK   (Tc / SPLIT)    // 512 t per CTA
#define NT1     128
#define W1      (NT1 / 32)      // 4 warps
#define GMAX    13              // max sensors per reduction group

// Per-batch partial sums, one row per CTA:
// [0..36]=sum x, [37..73]=sum mask, [74]=sum valid*time, [75]=sum valid
__device__ float        g_part[Bc][SPLIT][80];
__device__ unsigned int g_cnt[Bc];   // zero-init; last arriver resets to 0

__global__ __launch_bounds__(NT1, 4)
void fused_all(const float* __restrict__ x,        // [B,S,T]
               const int*   __restrict__ smask,    // [B,S,T]
               const float* __restrict__ time_in,  // [B,T]
               const float* __restrict__ stat_in,  // [B,ST]
               const float* __restrict__ W_sensor, // [2S,D]
               const float* __restrict__ b_sensor, // [D]
               const float* __restrict__ W_time,   // [1,D]
               const float* __restrict__ b_time,   // [D]
               const float* __restrict__ W_static, // [ST,ST]
               const float* __restrict__ b_static, // [ST]
               const float* __restrict__ W_merge,  // [MERGED,MERGED]
               const float* __restrict__ b_merge,  // [MERGED]
               const float* __restrict__ W_cls,    // [MERGED,C]
               const float* __restrict__ b_cls,    // [C]
               float* __restrict__ out)            // [B,C]
{
    const int blk  = blockIdx.x;
    const int b    = blk >> 2;
    const int part = blk & (SPLIT - 1);
    const int tid  = threadIdx.x;
    const int lane = tid & 31;
    const int warp = tid >> 5;
    const int t0   = part * CHUNK + tid * 4;

    __shared__ float4 sens_s4[2][Dc / 4];        // 16B-aligned by type
    __shared__ float4 merge_s4[2][MERGEDc / 4];
    __shared__ float  st[W1][80];
    __shared__ float  sx[76];
    __shared__ float  comb[MERGEDc];
    __shared__ float  combr[MERGEDc];
    __shared__ int    is_last;

    // =====================================================================
    // Streaming phase — 3 sensor groups (13/12/12) to bound register life
    // =====================================================================
    int vflags = 0;   // validity bits for this thread's 4 t's (across ALL sensors)
    {
        const float4* xb = (const float4*)(x     + (size_t)b * Sc * Tc);
        const int4*   mb = (const int4*)  (smask + (size_t)b * Sc * Tc);

#pragma unroll 1
        for (int grp = 0; grp < 3; ++grp) {
            const int s0 = (grp == 0) ? 0 : (grp == 1) ? 13 : 25;
            const int ns = (grp == 0) ? 13 : 12;

            float ps[GMAX];
            float pmf[GMAX];
#pragma unroll
            for (int k = 0; k < GMAX; ++k) {
                ps[k] = 0.f; pmf[k] = 0.f;
                if (k < ns) {
                    const int s   = s0 + k;
                    const int idx = (s * Tc + t0) >> 2;
                    float4 xv = __ldg(&xb[idx]);
                    int4   mv = __ldg(&mb[idx]);
                    // valid[t]==0 => all features at t are 0 => plain sums ok
                    ps[k]  = (xv.x + xv.y) + (xv.z + xv.w);
                    pmf[k] = (float)((mv.x + mv.y) + (mv.z + mv.w));
                    vflags |= ((xv.x != 0.f) | (mv.x != 0)) ? 1 : 0;
                    vflags |= ((xv.y != 0.f) | (mv.y != 0)) ? 2 : 0;
                    vflags |= ((xv.z != 0.f) | (mv.z != 0)) ? 4 : 0;
                    vflags |= ((xv.w != 0.f) | (mv.w != 0)) ? 8 : 0;
                }
            }

            // butterfly-reduce this group's 2*ns values
#pragma unroll
            for (int k = 0; k < GMAX; ++k) {
                if (k < ns) {
#pragma unroll
                    for (int o = 16; o > 0; o >>= 1) {
                        ps[k]  += __shfl_xor_sync(0xFFFFFFFFu, ps[k],  o);
                        pmf[k] += __shfl_xor_sync(0xFFFFFFFFu, pmf[k], o);
                    }
                }
            }
            if (lane == 0) {
#pragma unroll
                for (int k = 0; k < GMAX; ++k) {
                    if (k < ns) {
                        st[warp][s0 + k]      = ps[k];
                        st[warp][Sc + s0 + k] = pmf[k];
                    }
                }
            }
            __syncthreads();   // also blocks load hoisting across groups
        }

        // ---- time / denom from accumulated validity
        float4 tv = __ldg((const float4*)(time_in + (size_t)b * Tc) + (t0 >> 2));
        const float f0 = (float)(vflags & 1);
        const float f1 = (float)((vflags >> 1) & 1);
        const float f2 = (float)((vflags >> 2) & 1);
        const float f3 = (float)((vflags >> 3) & 1);
        float tsum = f0 * tv.x + f1 * tv.y + f2 * tv.z + f3 * tv.w;
        float den  = f0 + f1 + f2 + f3;
#pragma unroll
        for (int o = 16; o > 0; o >>= 1) {
            tsum += __shfl_xor_sync(0xFFFFFFFFu, tsum, o);
            den  += __shfl_xor_sync(0xFFFFFFFFu, den,  o);
        }
        if (lane == 0) {
            st[warp][Fc]     = tsum;
            st[warp][Fc + 1] = den;
        }
        __syncthreads();

        if (tid < 76) {
            g_part[b][part][tid] = (st[0][tid] + st[1][tid])
                                 + (st[2][tid] + st[3][tid]);
            __threadfence();        // publish before election
        }
    }

    // =====================================================================
    // Last-CTA-per-batch election
    // =====================================================================
    __syncthreads();
    if (tid == 0) {
        unsigned int old = atomicAdd(&g_cnt[b], 1u);
        is_last = (old == SPLIT - 1);
        if (is_last) g_cnt[b] = 0;   // self-reset for next graph replay
    }
    __syncthreads();
    if (!is_last) return;
    __threadfence();                 // acquire side

    // =====================================================================
    // MLP head for batch b (overlaps other batches' streaming)
    // =====================================================================
    if (tid < 76) {
        sx[tid] = (g_part[b][0][tid] + g_part[b][1][tid])
                + (g_part[b][2][tid] + g_part[b][3][tid]);
    }
    __syncthreads();

    const float denomR = sx[Fc + 1];
    const float denomC = fmaxf(denomR, 1e-9f);
    const float tsumR  = sx[Fc];

    // ---- sensor projection: 2 f-groups (37 each) x 64 d-quads, float4
    {
        const int g  = tid >> 6;
        const int q  = tid & 63;
        const int f0 = g * 37;
        float4 acc = make_float4(0.f, 0.f, 0.f, 0.f);
#pragma unroll 4
        for (int k = 0; k < 37; ++k) {
            const float  s = sx[f0 + k];
            const float4 w = __ldg((const float4*)(W_sensor + (f0 + k) * Dc) + q);
            acc.x += s * w.x; acc.y += s * w.y;
            acc.z += s * w.z; acc.w += s * w.w;
        }
        sens_s4[g][q] = acc;
    }
    __syncthreads();

    {
        const float* s0p = (const float*)sens_s4[0];
        const float* s1p = (const float*)sens_s4[1];
        for (int d = tid; d < Dc; d += NT1) {
            float a = s0p[d] + s1p[d]
                    + tsumR  * __ldg(&W_time[d])
                    + denomR * (__ldg(&b_sensor[d]) + __ldg(&b_time[d]));
            comb[d] = a / denomC;
        }
    }
    if (tid < STc) {
        const int j = tid;
        float a = __ldg(&b_static[j]);
#pragma unroll
        for (int i = 0; i < STc; ++i)
            a += __ldg(&stat_in[b * STc + i]) * __ldg(&W_static[i * STc + j]);
        comb[Dc + j] = a;
    }
    __syncthreads();

    // ---- merge: 2 i-groups (132 each) x 66 j-quads, float4
    {
        const int g  = tid >> 6;
        const int q  = tid & 63;
        const int i0 = g * 132;
        float4 acc = make_float4(0.f, 0.f, 0.f, 0.f);
#pragma unroll 4
        for (int k = 0; k < 132; ++k) {
            const float  c = comb[i0 + k];
            const float4 w = __ldg((const float4*)(W_merge + (i0 + k) * MERGEDc) + q);
            acc.x += c * w.x; acc.y += c * w.y;
            acc.z += c * w.z; acc.w += c * w.w;
        }
        merge_s4[g][q] = acc;

        if (tid < 4) {               // tail quads 64,65 for both i-groups
            const int gg  = tid >> 1;
            const int qq  = 64 + (tid & 1);
            const int ii0 = gg * 132;
            float4 a2 = make_float4(0.f, 0.f, 0.f, 0.f);
#pragma unroll 4
            for (int k = 0; k < 132; ++k) {
                const float  c = comb[ii0 + k];
                const float4 w = __ldg((const float4*)(W_merge + (ii0 + k) * MERGEDc) + qq);
                a2.x += c * w.x; a2.y += c * w.y;
                a2.z += c * w.z; a2.w += c * w.w;
            }
            merge_s4[gg][qq] = a2;
        }
    }
    __syncthreads();

    {
        const float* m0 = (const float*)merge_s4[0];
        const float* m1 = (const float*)merge_s4[1];
        for (int j = tid; j < MERGEDc; j += NT1) {
            float a = __ldg(&b_merge[j]) + m0[j] + m1[j];
            combr[j] = fmaxf(a, 0.f);
        }
    }
    __syncthreads();

    if (tid < 32) {
        float c0 = 0.f, c1 = 0.f;
        for (int i = lane; i < MERGEDc; i += 32) {
            const float v = combr[i];
            c0 += v * __ldg(&W_cls[i * Cc + 0]);
            c1 += v * __ldg(&W_cls[i * Cc + 1]);
        }
#pragma unroll
        for (int o = 16; o > 0; o >>= 1) {
            c0 += __shfl_xor_sync(0xFFFFFFFFu, c0, o);
            c1 += __shfl_xor_sync(0xFFFFFFFFu, c1, o);
        }
        if (lane == 0) {
            out[b * Cc + 0] = c0 + __ldg(&b_cls[0]);
            out[b * Cc + 1] = c1 + __ldg(&b_cls[1]);
        }
    }
}

extern "C" void kernel_launch(void* const* d_in, const int* in_sizes, int n_in,
                              void* d_out, int out_size)
{
    const float* x        = (const float*)d_in[0];
    const float* stat_in  = (const float*)d_in[1];
    const float* time_in  = (const float*)d_in[2];
    const int*   smask    = (const int*)  d_in[3];
    const float* W_sensor = (const float*)d_in[4];
    const float* b_sensor = (const float*)d_in[5];
    const float* W_time   = (const float*)d_in[6];
    const float* b_time   = (const float*)d_in[7];
    const float* W_static = (const float*)d_in[8];
    const float* b_static = (const float*)d_in[9];
    const float* W_merge  = (const float*)d_in[10];
    const float* b_merge  = (const float*)d_in[11];
    const float* W_cls    = (const float*)d_in[12];
    const float* b_cls    = (const float*)d_in[13];
    float* out = (float*)d_out;

    fused_all<<<Bc * SPLIT, NT1>>>(x, smask, time_in, stat_in,
                                   W_sensor, b_sensor, W_time, b_time,
                                   W_static, b_static, W_merge, b_merge,
                                   W_cls, b_cls, out);
}

// round 11
// speedup vs baseline: 1.6267x; 1.6267x over previous
#include <cuda_runtime.h>

#define Bc      128
#define Sc      37
#define Tc      2048
#define Dc      256
#define STc     8
#define Cc      2
#define Fc      (2 * Sc)        // 74
#define MERGEDc (Dc + STc)      // 264
#define SPLIT   4
#define CHUNK   (Tc / SPLIT)    // 512 t per CTA
#define NT1     256
#define W1      (NT1 / 32)      // 8 warps
#define NT2     1024
#define NG      15              // reduction groups in phase2

// Per-batch partial sums, one row per phase1 CTA:
// [0..36]=sum x, [37..73]=sum mask, [74]=sum valid*time, [75]=sum valid
__device__ float g_part[Bc][SPLIT][80];

// ---------------------------------------------------------------------------
// Phase 1: warp-per-sensor streaming sums (low-reg, high-occupancy)
// ---------------------------------------------------------------------------
__global__ __launch_bounds__(NT1, 6)
void phase1(const float* __restrict__ x,        // [B,S,T]
            const int*   __restrict__ smask,    // [B,S,T]
            const float* __restrict__ time_in)  // [B,T]
{
    const int blk   = blockIdx.x;
    const int b     = blk >> 2;
    const int part  = blk & (SPLIT - 1);
    const int tid   = threadIdx.x;
    const int lane  = tid & 31;
    const int warp  = tid >> 5;
    const int tbase = part * CHUNK;

    __shared__ float ssum[Fc];       // [0..36]=x sums, [37..73]=mask sums
    __shared__ int   vmsh[W1][32];   // per-warp validity bitmasks
    __shared__ float td[2];          // tsum, den

    const float* xb = x     + (size_t)b * Sc * Tc;
    const int*   mb = smask + (size_t)b * Sc * Tc;

    unsigned vmask = 0;   // 16 bits: validity of this lane's 16 t's (4 iters x 4)

    // ---- sensor passes: warp w handles sensors w, w+8, w+16, w+24, w+32
#pragma unroll
    for (int k = 0; k < 5; ++k) {
        const int s = warp + 8 * k;
        if (s < Sc) {
            float xacc = 0.f;
            int   macc = 0;
#pragma unroll
            for (int it = 0; it < 4; ++it) {
                const int t = tbase + it * 128 + lane * 4;
                const float4 xv = __ldg((const float4*)(xb + (size_t)s * Tc + t));
                const int4   mv = __ldg((const int4*)  (mb + (size_t)s * Tc + t));
                // valid[t]==0 => all features at t are 0 => plain sums == masked sums
                xacc += (xv.x + xv.y) + (xv.z + xv.w);
                macc += (mv.x + mv.y) + (mv.z + mv.w);
                unsigned bits = (((xv.x != 0.f) | (mv.x != 0)) ? 1u : 0u)
                              | (((xv.y != 0.f) | (mv.y != 0)) ? 2u : 0u)
                              | (((xv.z != 0.f) | (mv.z != 0)) ? 4u : 0u)
                              | (((xv.w != 0.f) | (mv.w != 0)) ? 8u : 0u);
                vmask |= bits << (it * 4);
            }
            float maccf = (float)macc;
#pragma unroll
            for (int o = 16; o > 0; o >>= 1) {
                xacc  += __shfl_xor_sync(0xFFFFFFFFu, xacc,  o);
                maccf += __shfl_xor_sync(0xFFFFFFFFu, maccf, o);
            }
            if (lane == 0) {
                ssum[s]      = xacc;     // warp owns full t-chunk: no cross-warp reduce
                ssum[Sc + s] = maccf;
            }
        }
    }
    vmsh[warp][lane] = (int)vmask;
    __syncthreads();

    // ---- warp 0: OR validity across warps, then tsum/den
    if (warp == 0) {
        unsigned v = 0;
#pragma unroll
        for (int w = 0; w < W1; ++w) v |= (unsigned)vmsh[w][lane];
        const float* tb = time_in + (size_t)b * Tc;
        float tsum = 0.f;
        float den  = (float)__popc(v);
#pragma unroll
        for (int it = 0; it < 4; ++it) {
            const float4 tv = __ldg((const float4*)(tb + tbase + it * 128 + lane * 4));
            const unsigned bb = (v >> (it * 4)) & 0xFu;
            tsum += ((bb & 1u) ? tv.x : 0.f) + ((bb & 2u) ? tv.y : 0.f)
                  + ((bb & 4u) ? tv.z : 0.f) + ((bb & 8u) ? tv.w : 0.f);
        }
#pragma unroll
        for (int o = 16; o > 0; o >>= 1) {
            tsum += __shfl_xor_sync(0xFFFFFFFFu, tsum, o);
            den  += __shfl_xor_sync(0xFFFFFFFFu, den,  o);
        }
        if (lane == 0) { td[0] = tsum; td[1] = den; }
    }
    __syncthreads();

    if (tid < Fc)            g_part[b][part][tid]    = ssum[tid];
    else if (tid == Fc)      g_part[b][part][Fc]     = td[0];
    else if (tid == Fc + 1)  g_part[b][part][Fc + 1] = td[1];
}

// ---------------------------------------------------------------------------
// Phase 2: MLP head (proven R6 version, float4-vectorized, wide splits)
// ---------------------------------------------------------------------------
__global__ __launch_bounds__(NT2, 1)
void phase2(const float* __restrict__ stat_in,  // [B,ST]
            const float* __restrict__ W_sensor, // [2S,D]
            const float* __restrict__ b_sensor, // [D]
            const float* __restrict__ W_time,   // [1,D]
            const float* __restrict__ b_time,   // [D]
            const float* __restrict__ W_static, // [ST,ST]
            const float* __restrict__ b_static, // [ST]
            const float* __restrict__ W_merge,  // [MERGED,MERGED]
            const float* __restrict__ b_merge,  // [MERGED]
            const float* __restrict__ W_cls,    // [MERGED,C]
            const float* __restrict__ b_cls,    // [C]
            float* __restrict__ out)            // [B,C]
{
    const int b    = blockIdx.x;
    const int tid  = threadIdx.x;
    const int lane = tid & 31;

    __shared__ float sx[76];
    __shared__ float comb[MERGEDc];
    __shared__ float combr[MERGEDc];
    __shared__ float4 sens_s4[NG][Dc / 4];       // float4-typed => aligned
    __shared__ float4 merge_s4[NG][MERGEDc / 4];

    if (tid < 76) {
        sx[tid] = (g_part[b][0][tid] + g_part[b][1][tid])
                + (g_part[b][2][tid] + g_part[b][3][tid]);
    }
    __syncthreads();

    const float denomR = sx[Fc + 1];
    const float denomC = fmaxf(denomR, 1e-9f);
    const float tsumR  = sx[Fc];

    // ---- sensor projection partials: 15 f-groups x 64 d-quads (float4)
    if (tid < NG * 64) {
        const int g  = tid >> 6;
        const int q  = tid & 63;
        const int f0 = g * 5;
        float4 acc = make_float4(0.f, 0.f, 0.f, 0.f);
#pragma unroll
        for (int k = 0; k < 5; ++k) {
            const int f = f0 + k;
            if (f < Fc) {
                const float  s = sx[f];
                const float4 w = __ldg((const float4*)(W_sensor + f * Dc) + q);
                acc.x += s * w.x; acc.y += s * w.y;
                acc.z += s * w.z; acc.w += s * w.w;
            }
        }
        sens_s4[g][q] = acc;
    } else if (tid >= NG * 64 && tid < NG * 64 + STc) {
        const int j = tid - NG * 64;
        float a = __ldg(&b_static[j]);
#pragma unroll
        for (int i = 0; i < STc; ++i)
            a += __ldg(&stat_in[b * STc + i]) * __ldg(&W_static[i * STc + j]);
        comb[Dc + j] = a;
    }
    __syncthreads();

    if (tid < Dc) {
        const int d = tid;
        float a = 0.f;
#pragma unroll
        for (int p = 0; p < NG; ++p) a += ((const float*)sens_s4[p])[d];
        a += tsumR  * __ldg(&W_time[d])
           + denomR * (__ldg(&b_sensor[d]) + __ldg(&b_time[d]));
        comb[d] = a / denomC;
    }
    __syncthreads();

    // ---- merge partials: 15 i-groups x 66 j-quads (float4)
    if (tid < NG * 66) {
        const int g  = tid / 66;
        const int q  = tid % 66;
        const int i0 = g * 18;
        const int ni = (g == 14) ? 12 : 18;
        float4 acc = make_float4(0.f, 0.f, 0.f, 0.f);
#pragma unroll 6
        for (int k = 0; k < ni; ++k) {
            const int   i = i0 + k;
            const float c = comb[i];
            const float4 w = __ldg((const float4*)(W_merge + i * MERGEDc) + q);
            acc.x += c * w.x; acc.y += c * w.y;
            acc.z += c * w.z; acc.w += c * w.w;
        }
        merge_s4[g][q] = acc;
    }
    __syncthreads();

    if (tid < MERGEDc) {
        const int j = tid;
        float a = __ldg(&b_merge[j]);
#pragma unroll
        for (int p = 0; p < NG; ++p) a += ((const float*)merge_s4[p])[j];
        combr[j] = fmaxf(a, 0.f);
    }
    __syncthreads();

    if (tid < 32) {
        float c0 = 0.f, c1 = 0.f;
        for (int i = lane; i < MERGEDc; i += 32) {
            const float v = combr[i];
            c0 += v * __ldg(&W_cls[i * Cc + 0]);
            c1 += v * __ldg(&W_cls[i * Cc + 1]);
        }
#pragma unroll
        for (int o = 16; o > 0; o >>= 1) {
            c0 += __shfl_xor_sync(0xFFFFFFFFu, c0, o);
            c1 += __shfl_xor_sync(0xFFFFFFFFu, c1, o);
        }
        if (lane == 0) {
            out[b * Cc + 0] = c0 + __ldg(&b_cls[0]);
            out[b * Cc + 1] = c1 + __ldg(&b_cls[1]);
        }
    }
}

extern "C" void kernel_launch(void* const* d_in, const int* in_sizes, int n_in,
                              void* d_out, int out_size)
{
    const float* x        = (const float*)d_in[0];
    const float* stat_in  = (const float*)d_in[1];
    const float* time_in  = (const float*)d_in[2];
    const int*   smask    = (const int*)  d_in[3];
    const float* W_sensor = (const float*)d_in[4];
    const float* b_sensor = (const float*)d_in[5];
    const float* W_time   = (const float*)d_in[6];
    const float* b_time   = (const float*)d_in[7];
    const float* W_static = (const float*)d_in[8];
    const float* b_static = (const float*)d_in[9];
    const float* W_merge  = (const float*)d_in[10];
    const float* b_merge  = (const float*)d_in[11];
    const float* W_cls    = (const float*)d_in[12];
    const float* b_cls    = (const float*)d_in[13];
    float* out = (float*)d_out;

    phase1<<<Bc * SPLIT, NT1>>>(x, smask, time_in);
    phase2<<<Bc, NT2>>>(stat_in, W_sensor, b_sensor, W_time, b_time,
                        W_static, b_static, W_merge, b_merge,
                        W_cls, b_cls, out);
}